// round 4
// baseline (speedup 1.0000x reference)
#include <cuda_runtime.h>
#include <cuda_bf16.h>
#include <cstdint>

// Problem constants
#define IN_DIM 10
#define H_DIM  100
#define OUT_DIM 10
#define L_NUM  5
#define B_NUM  64
#define T_NUM  2048
#define M_ROWS (B_NUM * T_NUM)   // 131072

// Ping-pong layer activation buffers: [B, T, H] each (52.4 MB).
__device__ float g_bufA[(size_t)B_NUM * T_NUM * H_DIM];
__device__ float g_bufB[(size_t)B_NUM * T_NUM * H_DIM];

// ---------------------------------------------------------------------------
// f32x2 packed helpers (FFMA2 only reachable via PTX fma.rn.f32x2)
// ---------------------------------------------------------------------------
__device__ __forceinline__ unsigned long long fma2(unsigned long long a,
                                                   unsigned long long b,
                                                   unsigned long long c) {
    unsigned long long d;
    asm("fma.rn.f32x2 %0, %1, %2, %3;" : "=l"(d) : "l"(a), "l"(b), "l"(c));
    return d;
}
__device__ __forceinline__ unsigned long long add2(unsigned long long a,
                                                   unsigned long long b) {
    unsigned long long d;
    asm("add.rn.f32x2 %0, %1, %2;" : "=l"(d) : "l"(a), "l"(b));
    return d;
}
__device__ __forceinline__ unsigned long long pack2(float lo, float hi) {
    unsigned long long d;
    asm("mov.b64 %0, {%1, %2};" : "=l"(d) : "f"(lo), "f"(hi));
    return d;
}
__device__ __forceinline__ void unpack2(unsigned long long a, float& lo, float& hi) {
    asm("mov.b64 {%0, %1}, %2;" : "=f"(lo), "=f"(hi) : "l"(a));
}

// ---------------------------------------------------------------------------
// Input-transform GEMM:  Y[M][100] = X[M][Din] @ W^T + (b1 + b2)
// W row-major [100][Din]. Wt staged transposed in shared ([k][j], ld=100
// floats, 400B rows -> 16B aligned). One thread per row, 50 f32x2 register
// accumulators, broadcast LDS.128 reads of W pairs.
// ---------------------------------------------------------------------------
__global__ void __launch_bounds__(128) gemm_kernel(
    const float* __restrict__ X, const float* __restrict__ W,
    const float* __restrict__ b1, const float* __restrict__ b2,
    float* __restrict__ Y, int M, int Din)
{
    __shared__ __align__(16) float Ws[H_DIM * H_DIM];  // up to 40 KB used: [Din][100]
    __shared__ __align__(16) float bs[H_DIM];

    const int tid = threadIdx.x;
    for (int idx = tid; idx < Din * H_DIM; idx += 128) {
        int j = idx / Din;
        int k = idx - j * Din;
        Ws[k * H_DIM + j] = W[idx];          // W[j][k] -> Ws[k][j]
    }
    if (tid < H_DIM) bs[tid] = b1[tid] + b2[tid];
    __syncthreads();

    const int row = blockIdx.x * 128 + tid;
    if (row >= M) return;

    unsigned long long acc[50];
    const unsigned long long* bp = (const unsigned long long*)bs;
#pragma unroll
    for (int i = 0; i < 50; i++) acc[i] = bp[i];

    const float* xr = X + (size_t)row * Din;
#pragma unroll 1
    for (int k = 0; k < Din; k++) {
        float xk = xr[k];
        unsigned long long xkk = pack2(xk, xk);
        const ulonglong2* wr = (const ulonglong2*)(Ws + k * H_DIM);
#pragma unroll
        for (int i = 0; i < 25; i++) {
            ulonglong2 wv = wr[i];
            acc[2 * i]     = fma2(xkk, wv.x, acc[2 * i]);
            acc[2 * i + 1] = fma2(xkk, wv.y, acc[2 * i + 1]);
        }
    }
    unsigned long long* yr = (unsigned long long*)(Y + (size_t)row * H_DIM);
#pragma unroll
    for (int i = 0; i < 50; i++) yr[i] = acc[i];
}

// ---------------------------------------------------------------------------
// Recurrent kernel: one CTA per batch element, loops t = 0..T-1 in-kernel.
// In-place on xp buffer: reads xp[b][t][j], writes h_t[j] back to the same
// slot. h double-buffered in shared; Whh row j (50 f32x2 pairs) held in
// registers per thread. One __syncthreads per step.
// ---------------------------------------------------------------------------
__global__ void __launch_bounds__(128, 1) rnn_kernel(
    float* __restrict__ xp,            // [B,T,H], in-place
    const float* __restrict__ Whh,     // [H,H] this layer
    const float* __restrict__ h0,      // [B,H] this layer
    float* __restrict__ hfin)          // [B,H] final-hidden output slot
{
    const int b = blockIdx.x;
    const int j = threadIdx.x;

    __shared__ __align__(16) float hs[2][104];  // 416B rows -> 16B aligned

    unsigned long long w[50];
    if (j < H_DIM) {
        const unsigned long long* wr = (const unsigned long long*)(Whh + j * H_DIM);
#pragma unroll
        for (int i = 0; i < 50; i++) w[i] = wr[i];
        hs[0][j] = h0[b * H_DIM + j];
    } else if (j < 104) {
        hs[0][j] = 0.f;
        hs[1][j] = 0.f;
    }
    __syncthreads();

    float* xrow = xp + (size_t)b * T_NUM * H_DIM;
    float xv = (j < H_DIM) ? xrow[j] : 0.f;

#pragma unroll 1
    for (int t = 0; t < T_NUM; t++) {
        // Prefetch next timestep's input contribution
        float xnext = 0.f;
        if (t + 1 < T_NUM && j < H_DIM) xnext = xrow[(size_t)(t + 1) * H_DIM + j];

        const int p = t & 1;
        if (j < H_DIM) {
            const ulonglong2* hp = (const ulonglong2*)hs[p];
            unsigned long long a0 = 0ull, a1 = 0ull, a2 = 0ull, a3 = 0ull;
#pragma unroll
            for (int i = 0; i < 25; i++) {
                ulonglong2 hv = hp[i];
                if (i & 1) {
                    a2 = fma2(w[2 * i],     hv.x, a2);
                    a3 = fma2(w[2 * i + 1], hv.y, a3);
                } else {
                    a0 = fma2(w[2 * i],     hv.x, a0);
                    a1 = fma2(w[2 * i + 1], hv.y, a1);
                }
            }
            unsigned long long s2 = add2(add2(a0, a2), add2(a1, a3));
            float slo, shi;
            unpack2(s2, slo, shi);
            float s = slo + shi + xv;
            // tanh(s) = 1 - 2/(e^{2s}+1); saturates correctly for |s| large
            float e  = __expf(2.0f * s);
            float th = 1.0f - __fdividef(2.0f, e + 1.0f);
            hs[p ^ 1][j] = th;
            xrow[(size_t)t * H_DIM + j] = th;   // layer output, in-place
        }
        xv = xnext;
        __syncthreads();
    }

    if (j < H_DIM) hfin[b * H_DIM + j] = hs[T_NUM & 1][j];
}

// ---------------------------------------------------------------------------
// Output projection: y[M][10] = Xin[M][100] @ Wout^T + bout
// Wt staged in shared with ld=12 floats (48B rows -> 16B aligned).
// ---------------------------------------------------------------------------
__global__ void __launch_bounds__(128) proj_kernel(
    const float* __restrict__ X, const float* __restrict__ Wout,
    const float* __restrict__ bout, float* __restrict__ Y, int M)
{
    __shared__ __align__(16) float Ws[H_DIM * 12];
    __shared__ __align__(16) float bs[12];

    const int tid = threadIdx.x;
    for (int i = tid; i < H_DIM * 12; i += 128) Ws[i] = 0.f;
    if (tid < 12) bs[tid] = (tid < OUT_DIM) ? bout[tid] : 0.f;
    __syncthreads();
    for (int idx = tid; idx < OUT_DIM * H_DIM; idx += 128) {
        int j = idx / H_DIM;
        int k = idx - j * H_DIM;
        Ws[k * 12 + j] = Wout[idx];
    }
    __syncthreads();

    const int row = blockIdx.x * 128 + tid;
    if (row >= M) return;

    unsigned long long acc[5];
    const unsigned long long* bp = (const unsigned long long*)bs;
#pragma unroll
    for (int i = 0; i < 5; i++) acc[i] = bp[i];

    const float4* xr = (const float4*)(X + (size_t)row * H_DIM);
#pragma unroll 1
    for (int k4 = 0; k4 < 25; k4++) {
        float4 xv = xr[k4];
        float xs[4] = {xv.x, xv.y, xv.z, xv.w};
#pragma unroll
        for (int u = 0; u < 4; u++) {
            int k = k4 * 4 + u;
            unsigned long long xkk = pack2(xs[u], xs[u]);
            const unsigned long long* wr = (const unsigned long long*)(Ws + k * 12);
#pragma unroll
            for (int i = 0; i < 5; i++) acc[i] = fma2(xkk, wr[i], acc[i]);
        }
    }
    unsigned long long* yr = (unsigned long long*)(Y + (size_t)row * OUT_DIM);
#pragma unroll
    for (int i = 0; i < 5; i++) yr[i] = acc[i];
}

// ---------------------------------------------------------------------------
// Launcher: layer-by-layer. xp GEMM into ping-pong buffer, recurrent kernel
// in-place, alternate buffers; final projection into d_out. h_finals appended
// after y in d_out (tuple order: y, then stacked h_finals).
// ---------------------------------------------------------------------------
extern "C" void kernel_launch(void* const* d_in, const int* in_sizes, int n_in,
                              void* d_out, int out_size)
{
    const float* x    = (const float*)d_in[0];
    const float* h0   = (const float*)d_in[1];   // [L,B,H]
    const float* Wih0 = (const float*)d_in[2];   // [H,IN]
    const float* Wih  = (const float*)d_in[3];   // [L-1,H,H]
    const float* Whh  = (const float*)d_in[4];   // [L,H,H]
    const float* bih  = (const float*)d_in[5];   // [L,H]
    const float* bhh  = (const float*)d_in[6];   // [L,H]
    const float* Wout = (const float*)d_in[7];   // [OUT,H]
    const float* bout = (const float*)d_in[8];   // [OUT]

    float* y  = (float*)d_out;                       // [B,T,OUT]
    float* hf = y + (size_t)B_NUM * T_NUM * OUT_DIM; // [L,B,H]

    float *bufA, *bufB;
    cudaGetSymbolAddress((void**)&bufA, g_bufA);
    cudaGetSymbolAddress((void**)&bufB, g_bufB);

    const int M = M_ROWS;
    const int gemm_blocks = (M + 127) / 128;

    // Layer 0: input transform from x (Din=10)
    gemm_kernel<<<gemm_blocks, 128>>>(x, Wih0, bih, bhh, bufA, M, IN_DIM);
    rnn_kernel<<<B_NUM, 128>>>(bufA, Whh, h0, hf);

    float* cur = bufA;
    float* nxt = bufB;
    for (int l = 1; l < L_NUM; l++) {
        gemm_kernel<<<gemm_blocks, 128>>>(cur, Wih + (size_t)(l - 1) * H_DIM * H_DIM,
                                          bih + l * H_DIM, bhh + l * H_DIM,
                                          nxt, M, H_DIM);
        rnn_kernel<<<B_NUM, 128>>>(nxt, Whh + (size_t)l * H_DIM * H_DIM,
                                   h0 + (size_t)l * B_NUM * H_DIM,
                                   hf + (size_t)l * B_NUM * H_DIM);
        float* tmp = cur; cur = nxt; nxt = tmp;
    }

    proj_kernel<<<gemm_blocks, 128>>>(cur, Wout, bout, y, M);
}